// round 16
// baseline (speedup 1.0000x reference)
#include <cuda_runtime.h>
#include <cuda_bf16.h>
#include <math.h>
#include <stdint.h>

#define BB 2
#define TT 2048
#define CC 1024
#define HH 16
#define DD 64
#define C3 (3*CC)
#define MM (BB*TT)   // 4096

// ---------------- scratch (__device__ globals; allocation-free rule) -------
__device__ __nv_bfloat16 g_qkvh[(size_t)MM * C3];      // qkv hi [4096,3072]
__device__ __nv_bfloat16 g_qkvl[(size_t)MM * C3];      // qkv lo
__device__ __nv_bfloat16 g_xh[(size_t)MM * CC];
__device__ __nv_bfloat16 g_xl[(size_t)MM * CC];
__device__ __nv_bfloat16 g_wqkvT_h[(size_t)C3 * CC];   // w_qkv^T [3072,1024]
__device__ __nv_bfloat16 g_wqkvT_l[(size_t)C3 * CC];
__device__ __nv_bfloat16 g_wprojT_h[(size_t)CC * CC];  // w_proj^T [1024,1024]
__device__ __nv_bfloat16 g_wprojT_l[(size_t)CC * CC];
__device__ __nv_bfloat16 g_yh[(size_t)MM * CC];
__device__ __nv_bfloat16 g_yl[(size_t)MM * CC];

// ---------------- PTX helpers (baseline compute_103-legal) -----------------
__device__ __forceinline__ uint32_t smem_u32(const void* p) {
    uint32_t a;
    asm("{ .reg .u64 t; cvta.to.shared.u64 t, %1; cvt.u32.u64 %0, t; }"
        : "=r"(a) : "l"(p));
    return a;
}
__device__ __forceinline__ void cp16(uint32_t s, const void* g) {
    asm volatile("cp.async.cg.shared.global [%0], [%1], 16;"
                 :: "r"(s), "l"(g) : "memory");
}
__device__ __forceinline__ void cp_commit() {
    asm volatile("cp.async.commit_group;" ::: "memory");
}
template <int N>
__device__ __forceinline__ void cp_wait() {
    asm volatile("cp.async.wait_group %0;" :: "n"(N) : "memory");
}
__device__ __forceinline__ void ldm_x4(uint32_t* r, uint32_t a) {
    asm volatile("ldmatrix.sync.aligned.m8n8.x4.shared.b16 {%0,%1,%2,%3}, [%4];"
                 : "=r"(r[0]), "=r"(r[1]), "=r"(r[2]), "=r"(r[3]) : "r"(a));
}
__device__ __forceinline__ void ldm_x4_t(uint32_t* r, uint32_t a) {
    asm volatile("ldmatrix.sync.aligned.m8n8.x4.trans.shared.b16 {%0,%1,%2,%3}, [%4];"
                 : "=r"(r[0]), "=r"(r[1]), "=r"(r[2]), "=r"(r[3]) : "r"(a));
}
__device__ __forceinline__ void ldm_x2(uint32_t* r, uint32_t a) {
    asm volatile("ldmatrix.sync.aligned.m8n8.x2.shared.b16 {%0,%1}, [%2];"
                 : "=r"(r[0]), "=r"(r[1]) : "r"(a));
}
__device__ __forceinline__ void mma16816(float* c, const uint32_t* a, const uint32_t* b) {
    asm volatile(
        "mma.sync.aligned.m16n8k16.row.col.f32.bf16.bf16.f32 "
        "{%0,%1,%2,%3}, {%4,%5,%6,%7}, {%8,%9}, {%0,%1,%2,%3};"
        : "+f"(c[0]), "+f"(c[1]), "+f"(c[2]), "+f"(c[3])
        : "r"(a[0]), "r"(a[1]), "r"(a[2]), "r"(a[3]), "r"(b[0]), "r"(b[1]));
}
__device__ __forceinline__ void split_pack2(float a, float b, uint32_t& hi, uint32_t& lo) {
    __nv_bfloat16 ha = __float2bfloat16(a), hb = __float2bfloat16(b);
    __nv_bfloat16 la = __float2bfloat16(a - __bfloat162float(ha));
    __nv_bfloat16 lb = __float2bfloat16(b - __bfloat162float(hb));
    __nv_bfloat162 H(ha, hb), L(la, lb);
    hi = *(uint32_t*)&H; lo = *(uint32_t*)&L;
}

// ---------------------------------------------------------------------------
// Conversions
// ---------------------------------------------------------------------------
__global__ void convert_hl(const float* __restrict__ X,
                           __nv_bfloat16* __restrict__ H,
                           __nv_bfloat16* __restrict__ L) {
    int i = (blockIdx.x * blockDim.x + threadIdx.x) * 4;
    float4 v = *(const float4*)(X + i);
    float a[4] = {v.x, v.y, v.z, v.w};
    __nv_bfloat16 h[4], l[4];
#pragma unroll
    for (int j = 0; j < 4; j++) {
        h[j] = __float2bfloat16(a[j]);
        l[j] = __float2bfloat16(a[j] - __bfloat162float(h[j]));
    }
    *(__nv_bfloat162*)(H + i)     = __nv_bfloat162(h[0], h[1]);
    *(__nv_bfloat162*)(H + i + 2) = __nv_bfloat162(h[2], h[3]);
    *(__nv_bfloat162*)(L + i)     = __nv_bfloat162(l[0], l[1]);
    *(__nv_bfloat162*)(L + i + 2) = __nv_bfloat162(l[2], l[3]);
}

__global__ void transpose_convert(const float* __restrict__ W,
                                  __nv_bfloat16* __restrict__ Th,
                                  __nv_bfloat16* __restrict__ Tl,
                                  int K, int N) {
    __shared__ float t[32][33];
    int k0 = blockIdx.y * 32, n0 = blockIdx.x * 32;
    int tx = threadIdx.x, ty = threadIdx.y;
#pragma unroll
    for (int i = 0; i < 32; i += 8)
        t[ty + i][tx] = W[(size_t)(k0 + ty + i) * N + n0 + tx];
    __syncthreads();
#pragma unroll
    for (int i = 0; i < 32; i += 8) {
        float v = t[tx][ty + i];
        __nv_bfloat16 h = __float2bfloat16(v);
        __nv_bfloat16 l = __float2bfloat16(v - __bfloat162float(h));
        size_t o = (size_t)(n0 + ty + i) * K + k0 + tx;
        Th[o] = h; Tl[o] = l;
    }
}

// ---------------------------------------------------------------------------
// HMMA bf16x3 GEMM: 128x128 tile, 128 threads (4 warps, 64x64 warp tile),
// BK=32, 3-stage cp.async pipeline, XOR-swizzled 64B rows, one barrier
// per chunk. Split-product MMAs reordered for dependency distance 8.
// ---------------------------------------------------------------------------
#define GBK 32
#define GTILE 8192                     // 128 rows x 64B
#define GOFF_AH 0
#define GOFF_AL (1 * GTILE)
#define GOFF_BH (2 * GTILE)
#define GOFF_BL (3 * GTILE)
#define GSTAGE (4 * GTILE)             // 32768
#define GEMM_SMEM (3 * GSTAGE)         // 98304

// swizzled byte offset of 16B chunk (row, chunk) in a 128x64B tile
__device__ __forceinline__ uint32_t gsw(uint32_t row, uint32_t chunk) {
    return row * 64u + ((chunk ^ (row >> 1)) & 3u) * 16u;
}

template <bool SPLIT>
__global__ __launch_bounds__(128) void gemm_hmma(
    const __nv_bfloat16* __restrict__ Ah, const __nv_bfloat16* __restrict__ Al,
    const __nv_bfloat16* __restrict__ Bh, const __nv_bfloat16* __restrict__ Bl,
    float* __restrict__ C, __nv_bfloat16* __restrict__ Ch,
    __nv_bfloat16* __restrict__ Cl, int M, int N, int K)
{
    extern __shared__ __align__(128) char smem[];
    const uint32_t sb = smem_u32(smem);
    const int tid  = threadIdx.x;
    const int wid  = tid >> 5;
    const int lane = tid & 31;
    const int wm   = wid & 1;      // 0..1: 64-row half
    const int wn   = wid >> 1;     // 0..1: 64-col half
    const int bm   = blockIdx.y * 128;
    const int bn   = blockIdx.x * 128;

    const __nv_bfloat16* ah = Ah + (size_t)bm * K;
    const __nv_bfloat16* al = Al + (size_t)bm * K;
    const __nv_bfloat16* bh = Bh + (size_t)bn * K;
    const __nv_bfloat16* bl = Bl + (size_t)bn * K;

    float acc[4][8][4];
#pragma unroll
    for (int i = 0; i < 4; i++)
#pragma unroll
        for (int j = 0; j < 8; j++)
#pragma unroll
            for (int k = 0; k < 4; k++) acc[i][j][k] = 0.f;

    // loader: 512 16B-chunks per tile, 128 threads -> 4 chunks each, 4 tiles
    const uint32_t lr = (uint32_t)(tid >> 2);        // 0..31
    const uint32_t lc = (uint32_t)(tid & 3);
    uint32_t swo[4];
#pragma unroll
    for (int i = 0; i < 4; i++) swo[i] = gsw(lr + i * 32, lc);

    auto load_stage = [&](int slot, int k0) {
        const uint32_t s = sb + slot * GSTAGE;
#pragma unroll
        for (int i = 0; i < 4; i++) {
            const size_t go = (size_t)(lr + i * 32) * K + k0 + lc * 8;
            cp16(s + GOFF_AH + swo[i], ah + go);
            cp16(s + GOFF_AL + swo[i], al + go);
            cp16(s + GOFF_BH + swo[i], bh + go);
            cp16(s + GOFF_BL + swo[i], bl + go);
        }
    };

    // ldmatrix lane addressing (rows/chunks; swizzle applied at use)
    const int tb = lane & 15;
    const uint32_t b_row  = wn * 64 + (tb & 7);
    const uint32_t b_chnk = (uint32_t)(tb >> 3);
    const uint32_t a_row  = wm * 64 + (lane & 7) + ((lane >> 3) & 1) * 8;
    const uint32_t a_chnk = (uint32_t)(lane >> 4);

    load_stage(0, 0);
    cp_commit();
    load_stage(1, GBK);
    cp_commit();

    const int NCH = K / GBK;
    int slot = 0;
    for (int ch = 0; ch < NCH; ch++) {
        cp_wait<1>();
        __syncthreads();
        if (ch + 2 < NCH) {
            int nslot = slot + 2; if (nslot >= 3) nslot -= 3;
            load_stage(nslot, (ch + 2) * GBK);
        }
        cp_commit();     // exactly one group per iteration (may be empty at tail)

        const uint32_t s = sb + slot * GSTAGE;
#pragma unroll
        for (int ks = 0; ks < 2; ks++) {
            uint32_t bfh[8][2], bfl[8][2];
#pragma unroll
            for (int ni = 0; ni < 8; ni++) {
                uint32_t bo = gsw(b_row + ni * 8, b_chnk + ks * 2);
                ldm_x2(bfh[ni], s + GOFF_BH + bo);
                ldm_x2(bfl[ni], s + GOFF_BL + bo);
            }
#pragma unroll
            for (int mi = 0; mi < 4; mi++) {
                uint32_t ao = gsw(a_row + mi * 16, a_chnk + ks * 2);
                uint32_t afh[4], afl[4];
                ldm_x4(afh, s + GOFF_AH + ao);
                ldm_x4(afl, s + GOFF_AL + ao);
                // dependency distance 8: all ni per product
#pragma unroll
                for (int ni = 0; ni < 8; ni++) mma16816(acc[mi][ni], afh, bfh[ni]);
#pragma unroll
                for (int ni = 0; ni < 8; ni++) mma16816(acc[mi][ni], afh, bfl[ni]);
#pragma unroll
                for (int ni = 0; ni < 8; ni++) mma16816(acc[mi][ni], afl, bfh[ni]);
            }
        }
        slot = (slot == 2) ? 0 : slot + 1;
    }

    const int g = lane >> 2, q = lane & 3;
#pragma unroll
    for (int mi = 0; mi < 4; mi++) {
        const int row = bm + wm * 64 + mi * 16 + g;
#pragma unroll
        for (int ni = 0; ni < 8; ni++) {
            const int col = bn + wn * 64 + ni * 8 + q * 2;
            if (SPLIT) {
                uint32_t h0, l0, h1, l1;
                split_pack2(acc[mi][ni][0], acc[mi][ni][1], h0, l0);
                split_pack2(acc[mi][ni][2], acc[mi][ni][3], h1, l1);
                size_t o0 = (size_t)row * N + col;
                size_t o1 = (size_t)(row + 8) * N + col;
                *(uint32_t*)(Ch + o0) = h0; *(uint32_t*)(Cl + o0) = l0;
                *(uint32_t*)(Ch + o1) = h1; *(uint32_t*)(Cl + o1) = l1;
            } else {
                float* cp0 = C + (size_t)row * N + col;
                float* cp1 = C + (size_t)(row + 8) * N + col;
                *(float2*)cp0 = make_float2(acc[mi][ni][0], acc[mi][ni][1]);
                *(float2*)cp1 = make_float2(acc[mi][ni][2], acc[mi][ni][3]);
            }
        }
    }
}

// ---------------------------------------------------------------------------
// HMMA flash attention (causal; reference window term is dead code).
// ---------------------------------------------------------------------------
#define AROW 144
#define A_OQH 0
#define A_OQL (128 * AROW)
#define A_STG (2 * 128 * AROW)
#define A_TILE (64 * AROW)
#define A_STAGE_BYTES (4 * A_TILE)
#define ATT_SMEM (A_STG + 2 * A_STAGE_BYTES)

__global__ __launch_bounds__(256) void attn_hmma(
    const __nv_bfloat16* __restrict__ qh, const __nv_bfloat16* __restrict__ ql,
    __nv_bfloat16* __restrict__ yh, __nv_bfloat16* __restrict__ yl)
{
    extern __shared__ __align__(128) char smem[];
    const uint32_t sb = smem_u32(smem);
    const int tid = threadIdx.x, lane = tid & 31, w = tid >> 5;
    const int bh = blockIdx.x, b = bh >> 4, h = bh & 15;
    const int rt = gridDim.y - 1 - blockIdx.y;
    const int r0 = rt * 128;
    const int wq0 = r0 + w * 16;

    {
        const int qt = tid >> 7;
        const __nv_bfloat16* src = qt ? ql : qh;
        const uint32_t dst = sb + (qt ? A_OQL : A_OQH);
#pragma unroll
        for (int j = 0; j < 8; j++) {
            int idx = (tid & 127) + j * 128;
            int row = idx >> 3, col = idx & 7;
            cp16(dst + row * AROW + col * 16,
                 src + ((size_t)(b * TT + r0 + row)) * C3 + h * DD + col * 8);
        }
    }
    cp_commit();

    auto load_stage = [&](int buf, int k0) {
        const int t4 = tid >> 6;
        const __nv_bfloat16* src = (t4 & 1) ? ql : qh;
        const int voff = (t4 >> 1) ? 2 * CC : CC;
        const uint32_t dst = sb + A_STG + buf * A_STAGE_BYTES + t4 * A_TILE;
#pragma unroll
        for (int j = 0; j < 8; j++) {
            int idx = (tid & 63) + j * 64;
            int row = idx >> 3, col = idx & 7;
            cp16(dst + row * AROW + col * 16,
                 src + ((size_t)(b * TT + k0 + row)) * C3 + voff + h * DD + col * 8);
        }
    };

    load_stage(0, 0);
    cp_commit();
    cp_wait<1>();
    __syncthreads();

    uint32_t qfh[4][4], qfl[4][4];
    {
        const uint32_t q_row = w * 16 + (lane & 7) + ((lane >> 3) & 1) * 8;
#pragma unroll
        for (int ks = 0; ks < 4; ks++) {
            uint32_t qa = sb + A_OQH + q_row * AROW + (ks * 2 + (lane >> 4)) * 16;
            ldm_x4(qfh[ks], qa);
            ldm_x4(qfl[ks], qa + A_OQL);
        }
    }

    float o[8][4];
#pragma unroll
    for (int i = 0; i < 8; i++)
#pragma unroll
        for (int j = 0; j < 4; j++) o[i][j] = 0.f;
    float m0 = -1e30f, m1 = -1e30f, l0 = 0.f, l1 = 0.f;

    const uint32_t k_row  = (lane & 7) + (lane >> 4) * 8;
    const uint32_t k_half = (lane >> 3) & 1;
    const uint32_t v_key  = lane & 15;
    const int rg0 = wq0 + (lane >> 2), rg1 = rg0 + 8;
    const int qq2 = (lane & 3) * 2;

    const int NT = 2 * rt + 2;
    for (int ch = 0; ch < NT; ch++) {
        const int buf = ch & 1;
        if (ch + 1 < NT) {
            load_stage(buf ^ 1, (ch + 1) * 64);
            cp_commit();
            cp_wait<1>();
        } else {
            cp_wait<0>();
        }
        __syncthreads();

        const int k0 = ch * 64;
        if (k0 <= wq0) {
            const uint32_t stg = sb + A_STG + buf * A_STAGE_BYTES;

            float s[8][4];
#pragma unroll
            for (int i = 0; i < 8; i++)
#pragma unroll
                for (int j = 0; j < 4; j++) s[i][j] = 0.f;

#pragma unroll
            for (int ks = 0; ks < 4; ks++) {
#pragma unroll
                for (int np = 0; np < 4; np++) {
                    uint32_t ka = stg + (np * 16 + k_row) * AROW
                                + (ks * 2 + k_half) * 16;
                    uint32_t kh4[4], kl4[4];
                    ldm_x4(kh4, ka);
                    ldm_x4(kl4, ka + A_TILE);
                    // interleave the two accumulators: dependency distance 2
                    mma16816(s[2*np],   qfh[ks], kh4);
                    mma16816(s[2*np+1], qfh[ks], kh4 + 2);
                    mma16816(s[2*np],   qfh[ks], kl4);
                    mma16816(s[2*np+1], qfh[ks], kl4 + 2);
                    mma16816(s[2*np],   qfl[ks], kh4);
                    mma16816(s[2*np+1], qfl[ks], kh4 + 2);
                }
            }

            const bool need_mask = (wq0 - k0) < 64;
#pragma unroll
            for (int ni = 0; ni < 8; ni++) {
                int col = k0 + ni * 8 + qq2;
                float v0 = s[ni][0] * 0.125f, v1 = s[ni][1] * 0.125f;
                float v2 = s[ni][2] * 0.125f, v3 = s[ni][3] * 0.125f;
                if (need_mask) {
                    if (col     > rg0) v0 = -1e30f;
                    if (col + 1 > rg0) v1 = -1e30f;
                    if (col     > rg1) v2 = -1e30f;
                    if (col + 1 > rg1) v3 = -1e30f;
                }
                s[ni][0] = v0; s[ni][1] = v1; s[ni][2] = v2; s[ni][3] = v3;
            }

            float mx0 = -1e30f, mx1 = -1e30f;
#pragma unroll
            for (int ni = 0; ni < 8; ni++) {
                mx0 = fmaxf(mx0, fmaxf(s[ni][0], s[ni][1]));
                mx1 = fmaxf(mx1, fmaxf(s[ni][2], s[ni][3]));
            }
            mx0 = fmaxf(mx0, __shfl_xor_sync(0xffffffffu, mx0, 1));
            mx0 = fmaxf(mx0, __shfl_xor_sync(0xffffffffu, mx0, 2));
            mx1 = fmaxf(mx1, __shfl_xor_sync(0xffffffffu, mx1, 1));
            mx1 = fmaxf(mx1, __shfl_xor_sync(0xffffffffu, mx1, 2));

            float nm0 = fmaxf(m0, mx0), nm1 = fmaxf(m1, mx1);
            float cr0 = __expf(m0 - nm0), cr1 = __expf(m1 - nm1);
            float ps0 = 0.f, ps1 = 0.f;
#pragma unroll
            for (int ni = 0; ni < 8; ni++) {
                s[ni][0] = __expf(s[ni][0] - nm0);
                s[ni][1] = __expf(s[ni][1] - nm0);
                s[ni][2] = __expf(s[ni][2] - nm1);
                s[ni][3] = __expf(s[ni][3] - nm1);
                ps0 += s[ni][0] + s[ni][1];
                ps1 += s[ni][2] + s[ni][3];
            }
            ps0 += __shfl_xor_sync(0xffffffffu, ps0, 1);
            ps0 += __shfl_xor_sync(0xffffffffu, ps0, 2);
            ps1 += __shfl_xor_sync(0xffffffffu, ps1, 1);
            ps1 += __shfl_xor_sync(0xffffffffu, ps1, 2);
            l0 = l0 * cr0 + ps0;  l1 = l1 * cr1 + ps1;
            m0 = nm0;  m1 = nm1;
#pragma unroll
            for (int nd = 0; nd < 8; nd++) {
                o[nd][0] *= cr0; o[nd][1] *= cr0;
                o[nd][2] *= cr1; o[nd][3] *= cr1;
            }

#pragma unroll
            for (int ks = 0; ks < 4; ks++) {
                uint32_t ah[4], al[4];
                split_pack2(s[2*ks][0],   s[2*ks][1],   ah[0], al[0]);
                split_pack2(s[2*ks][2],   s[2*ks][3],   ah[1], al[1]);
                split_pack2(s[2*ks+1][0], s[2*ks+1][1], ah[2], al[2]);
                split_pack2(s[2*ks+1][2], s[2*ks+1][3], ah[3], al[3]);
#pragma unroll
                for (int np = 0; np < 4; np++) {
                    uint32_t va = stg + 2 * A_TILE + (ks * 16 + v_key) * AROW
                                + (np * 2 + (lane >> 4)) * 16;
                    uint32_t vh4[4], vl4[4];
                    ldm_x4_t(vh4, va);
                    ldm_x4_t(vl4, va + A_TILE);
                    // interleaved: dependency distance 2
                    mma16816(o[2*np],   ah, vh4);
                    mma16816(o[2*np+1], ah, vh4 + 2);
                    mma16816(o[2*np],   ah, vl4);
                    mma16816(o[2*np+1], ah, vl4 + 2);
                    mma16816(o[2*np],   al, vh4);
                    mma16816(o[2*np+1], al, vh4 + 2);
                }
            }
        }
        __syncthreads();
    }

    const float i0 = 1.f / l0, i1 = 1.f / l1;
    const size_t ob = ((size_t)(b * TT + rg0)) * CC + h * DD + qq2;
#pragma unroll
    for (int nd = 0; nd < 8; nd++) {
        uint32_t h0, lo0, h1, lo1;
        split_pack2(o[nd][0] * i0, o[nd][1] * i0, h0, lo0);
        split_pack2(o[nd][2] * i1, o[nd][3] * i1, h1, lo1);
        *(uint32_t*)(yh + ob + nd * 8) = h0;
        *(uint32_t*)(yl + ob + nd * 8) = lo0;
        *(uint32_t*)(yh + ob + 8 * CC + nd * 8) = h1;
        *(uint32_t*)(yl + ob + 8 * CC + nd * 8) = lo1;
    }
}

// ---------------------------------------------------------------------------
extern "C" void kernel_launch(void* const* d_in, const int* in_sizes, int n_in,
                              void* d_out, int out_size)
{
    const float* x      = (const float*)d_in[0];
    const float* w_qkv  = (const float*)d_in[1];
    const float* w_proj = (const float*)d_in[2];
    float* out = (float*)d_out;

    void *pqh, *pql, *pxh, *pxl, *pwqh, *pwql, *pwph, *pwpl, *pyh, *pyl;
    cudaGetSymbolAddress(&pqh, g_qkvh); cudaGetSymbolAddress(&pql, g_qkvl);
    cudaGetSymbolAddress(&pxh, g_xh);   cudaGetSymbolAddress(&pxl, g_xl);
    cudaGetSymbolAddress(&pwqh, g_wqkvT_h); cudaGetSymbolAddress(&pwql, g_wqkvT_l);
    cudaGetSymbolAddress(&pwph, g_wprojT_h); cudaGetSymbolAddress(&pwpl, g_wprojT_l);
    cudaGetSymbolAddress(&pyh, g_yh);   cudaGetSymbolAddress(&pyl, g_yl);

    cudaFuncSetAttribute(gemm_hmma<true>,
                         cudaFuncAttributeMaxDynamicSharedMemorySize, GEMM_SMEM);
    cudaFuncSetAttribute(gemm_hmma<false>,
                         cudaFuncAttributeMaxDynamicSharedMemorySize, GEMM_SMEM);
    cudaFuncSetAttribute(attn_hmma,
                         cudaFuncAttributeMaxDynamicSharedMemorySize, ATT_SMEM);

    convert_hl<<<(MM * CC) / (256 * 4), 256>>>(x, (__nv_bfloat16*)pxh, (__nv_bfloat16*)pxl);
    dim3 tcb(32, 8);
    transpose_convert<<<dim3(C3 / 32, CC / 32), tcb>>>(w_qkv,
        (__nv_bfloat16*)pwqh, (__nv_bfloat16*)pwql, CC, C3);
    transpose_convert<<<dim3(CC / 32, CC / 32), tcb>>>(w_proj,
        (__nv_bfloat16*)pwph, (__nv_bfloat16*)pwpl, CC, CC);

    gemm_hmma<true><<<dim3(C3 / 128, MM / 128), 128, GEMM_SMEM>>>(
        (const __nv_bfloat16*)pxh, (const __nv_bfloat16*)pxl,
        (const __nv_bfloat16*)pwqh, (const __nv_bfloat16*)pwql,
        nullptr, (__nv_bfloat16*)pqh, (__nv_bfloat16*)pql, MM, C3, CC);

    attn_hmma<<<dim3(BB * HH, TT / 128), 256, ATT_SMEM>>>(
        (const __nv_bfloat16*)pqh, (const __nv_bfloat16*)pql,
        (__nv_bfloat16*)pyh, (__nv_bfloat16*)pyl);

    gemm_hmma<false><<<dim3(CC / 128, MM / 128), 128, GEMM_SMEM>>>(
        (const __nv_bfloat16*)pyh, (const __nv_bfloat16*)pyl,
        (const __nv_bfloat16*)pwph, (const __nv_bfloat16*)pwpl,
        out, nullptr, nullptr, MM, CC, CC);
}

// round 17
// speedup vs baseline: 1.5567x; 1.5567x over previous
#include <cuda_runtime.h>
#include <cuda_bf16.h>
#include <cuda_fp16.h>
#include <math.h>
#include <stdint.h>

#define BB 2
#define TT 2048
#define CC 1024
#define HH 16
#define DD 64
#define C3 (3*CC)
#define MM (BB*TT)   // 4096

// ---------------- scratch (__device__ globals; allocation-free rule) -------
__device__ __half g_qkvh[(size_t)MM * C3];      // qkv hi fp16 [4096,3072]
__device__ __half g_qkvl[(size_t)MM * C3];      // qkv lo fp16
__device__ __half g_xh[(size_t)MM * CC];
__device__ __half g_xl[(size_t)MM * CC];
__device__ __half g_wqkvT[(size_t)C3 * CC];     // w_qkv^T fp16 (single)
__device__ __half g_wprojT[(size_t)CC * CC];    // w_proj^T fp16 (single)
__device__ __half g_yh[(size_t)MM * CC];
__device__ __half g_yl[(size_t)MM * CC];

// ---------------- PTX helpers (baseline compute_103-legal) -----------------
__device__ __forceinline__ uint32_t smem_u32(const void* p) {
    uint32_t a;
    asm("{ .reg .u64 t; cvta.to.shared.u64 t, %1; cvt.u32.u64 %0, t; }"
        : "=r"(a) : "l"(p));
    return a;
}
__device__ __forceinline__ void cp16(uint32_t s, const void* g) {
    asm volatile("cp.async.cg.shared.global [%0], [%1], 16;"
                 :: "r"(s), "l"(g) : "memory");
}
__device__ __forceinline__ void cp_commit() {
    asm volatile("cp.async.commit_group;" ::: "memory");
}
template <int N>
__device__ __forceinline__ void cp_wait() {
    asm volatile("cp.async.wait_group %0;" :: "n"(N) : "memory");
}
__device__ __forceinline__ void ldm_x4(uint32_t* r, uint32_t a) {
    asm volatile("ldmatrix.sync.aligned.m8n8.x4.shared.b16 {%0,%1,%2,%3}, [%4];"
                 : "=r"(r[0]), "=r"(r[1]), "=r"(r[2]), "=r"(r[3]) : "r"(a));
}
__device__ __forceinline__ void ldm_x4_t(uint32_t* r, uint32_t a) {
    asm volatile("ldmatrix.sync.aligned.m8n8.x4.trans.shared.b16 {%0,%1,%2,%3}, [%4];"
                 : "=r"(r[0]), "=r"(r[1]), "=r"(r[2]), "=r"(r[3]) : "r"(a));
}
__device__ __forceinline__ void ldm_x2(uint32_t* r, uint32_t a) {
    asm volatile("ldmatrix.sync.aligned.m8n8.x2.shared.b16 {%0,%1}, [%2];"
                 : "=r"(r[0]), "=r"(r[1]) : "r"(a));
}
// fp16 HMMA, fp32 accumulate
__device__ __forceinline__ void mma16816(float* c, const uint32_t* a, const uint32_t* b) {
    asm volatile(
        "mma.sync.aligned.m16n8k16.row.col.f32.f16.f16.f32 "
        "{%0,%1,%2,%3}, {%4,%5,%6,%7}, {%8,%9}, {%0,%1,%2,%3};"
        : "+f"(c[0]), "+f"(c[1]), "+f"(c[2]), "+f"(c[3])
        : "r"(a[0]), "r"(a[1]), "r"(a[2]), "r"(a[3]), "r"(b[0]), "r"(b[1]));
}
// fp32 -> (hi,lo) fp16 split, packed as __half2 words
__device__ __forceinline__ void split_pack2(float a, float b, uint32_t& hi, uint32_t& lo) {
    __half ha = __float2half_rn(a), hb = __float2half_rn(b);
    __half la = __float2half_rn(a - __half2float(ha));
    __half lb = __float2half_rn(b - __half2float(hb));
    __half2 H(ha, hb), L(la, lb);
    hi = *(uint32_t*)&H; lo = *(uint32_t*)&L;
}

// ---------------------------------------------------------------------------
// Conversions
// ---------------------------------------------------------------------------
__global__ void convert_hl(const float* __restrict__ X,
                           __half* __restrict__ H, __half* __restrict__ L) {
    int i = (blockIdx.x * blockDim.x + threadIdx.x) * 4;
    float4 v = *(const float4*)(X + i);
    uint32_t h0, l0, h1, l1;
    split_pack2(v.x, v.y, h0, l0);
    split_pack2(v.z, v.w, h1, l1);
    *(uint32_t*)(H + i)     = h0;  *(uint32_t*)(H + i + 2) = h1;
    *(uint32_t*)(L + i)     = l0;  *(uint32_t*)(L + i + 2) = l1;
}

// W [K,N] row-major -> Wt [N,K] single fp16
__global__ void transpose_convert(const float* __restrict__ W,
                                  __half* __restrict__ Th, int K, int N) {
    __shared__ float t[32][33];
    int k0 = blockIdx.y * 32, n0 = blockIdx.x * 32;
    int tx = threadIdx.x, ty = threadIdx.y;
#pragma unroll
    for (int i = 0; i < 32; i += 8)
        t[ty + i][tx] = W[(size_t)(k0 + ty + i) * N + n0 + tx];
    __syncthreads();
#pragma unroll
    for (int i = 0; i < 32; i += 8) {
        size_t o = (size_t)(n0 + ty + i) * K + k0 + tx;
        Th[o] = __float2half_rn(t[tx][ty + i]);
    }
}

// ---------------------------------------------------------------------------
// HMMA fp16 GEMM: C[M,N] = (Ah+Al)[M,K] @ B[N,K]^T   (B pre-rounded fp16)
// 128x128 tile, 128 threads (4 warps, 64x64 warp tile), BK=32, 3-stage
// cp.async pipeline, XOR-swizzled 64B rows, one barrier per chunk.
// 3 tiles/stage (Ah, Al, B) = 24KB; smem 72KB -> 2 CTAs/SM.
// ---------------------------------------------------------------------------
#define GBK 32
#define GTILE 8192                     // 128 rows x 64B
#define GOFF_AH 0
#define GOFF_AL (1 * GTILE)
#define GOFF_B  (2 * GTILE)
#define GSTAGE (3 * GTILE)             // 24576
#define GEMM_SMEM (3 * GSTAGE)         // 73728

__device__ __forceinline__ uint32_t gsw(uint32_t row, uint32_t chunk) {
    return row * 64u + ((chunk ^ (row >> 1)) & 3u) * 16u;
}

template <bool SPLIT>
__global__ __launch_bounds__(128) void gemm_hmma(
    const __half* __restrict__ Ah, const __half* __restrict__ Al,
    const __half* __restrict__ B,
    float* __restrict__ C, __half* __restrict__ Ch, __half* __restrict__ Cl,
    int M, int N, int K)
{
    extern __shared__ __align__(128) char smem[];
    const uint32_t sb = smem_u32(smem);
    const int tid  = threadIdx.x;
    const int wid  = tid >> 5;
    const int lane = tid & 31;
    const int wm   = wid & 1;
    const int wn   = wid >> 1;
    const int bm   = blockIdx.y * 128;
    const int bn   = blockIdx.x * 128;

    const __half* ah = Ah + (size_t)bm * K;
    const __half* al = Al + (size_t)bm * K;
    const __half* bp = B  + (size_t)bn * K;

    float acc[4][8][4];
#pragma unroll
    for (int i = 0; i < 4; i++)
#pragma unroll
        for (int j = 0; j < 8; j++)
#pragma unroll
            for (int k = 0; k < 4; k++) acc[i][j][k] = 0.f;

    // loader: per tile 512 16B-chunks, 128 threads -> 4 each, 3 tiles
    const uint32_t lr = (uint32_t)(tid >> 2);
    const uint32_t lc = (uint32_t)(tid & 3);
    uint32_t swo[4];
#pragma unroll
    for (int i = 0; i < 4; i++) swo[i] = gsw(lr + i * 32, lc);

    auto load_stage = [&](int slot, int k0) {
        const uint32_t s = sb + slot * GSTAGE;
#pragma unroll
        for (int i = 0; i < 4; i++) {
            const size_t go = (size_t)(lr + i * 32) * K + k0 + lc * 8;
            cp16(s + GOFF_AH + swo[i], ah + go);
            cp16(s + GOFF_AL + swo[i], al + go);
            cp16(s + GOFF_B  + swo[i], bp + go);
        }
    };

    const int tb = lane & 15;
    const uint32_t b_row  = wn * 64 + (tb & 7);
    const uint32_t b_chnk = (uint32_t)(tb >> 3);
    const uint32_t a_row  = wm * 64 + (lane & 7) + ((lane >> 3) & 1) * 8;
    const uint32_t a_chnk = (uint32_t)(lane >> 4);

    load_stage(0, 0);
    cp_commit();
    load_stage(1, GBK);
    cp_commit();

    const int NCH = K / GBK;
    int slot = 0;
    for (int ch = 0; ch < NCH; ch++) {
        cp_wait<1>();
        __syncthreads();
        if (ch + 2 < NCH) {
            int nslot = slot + 2; if (nslot >= 3) nslot -= 3;
            load_stage(nslot, (ch + 2) * GBK);
        }
        cp_commit();     // exactly one group per iteration (may be empty at tail)

        const uint32_t s = sb + slot * GSTAGE;
#pragma unroll
        for (int ks = 0; ks < 2; ks++) {
            uint32_t bf[8][2];
#pragma unroll
            for (int ni = 0; ni < 8; ni++) {
                uint32_t bo = gsw(b_row + ni * 8, b_chnk + ks * 2);
                ldm_x2(bf[ni], s + GOFF_B + bo);
            }
#pragma unroll
            for (int mi = 0; mi < 4; mi++) {
                uint32_t ao = gsw(a_row + mi * 16, a_chnk + ks * 2);
                uint32_t afh[4], afl[4];
                ldm_x4(afh, s + GOFF_AH + ao);
                ldm_x4(afl, s + GOFF_AL + ao);
#pragma unroll
                for (int ni = 0; ni < 8; ni++) mma16816(acc[mi][ni], afh, bf[ni]);
#pragma unroll
                for (int ni = 0; ni < 8; ni++) mma16816(acc[mi][ni], afl, bf[ni]);
            }
        }
        slot = (slot == 2) ? 0 : slot + 1;
    }

    const int g = lane >> 2, q = lane & 3;
#pragma unroll
    for (int mi = 0; mi < 4; mi++) {
        const int row = bm + wm * 64 + mi * 16 + g;
#pragma unroll
        for (int ni = 0; ni < 8; ni++) {
            const int col = bn + wn * 64 + ni * 8 + q * 2;
            if (SPLIT) {
                uint32_t h0, l0, h1, l1;
                split_pack2(acc[mi][ni][0], acc[mi][ni][1], h0, l0);
                split_pack2(acc[mi][ni][2], acc[mi][ni][3], h1, l1);
                size_t o0 = (size_t)row * N + col;
                size_t o1 = (size_t)(row + 8) * N + col;
                *(uint32_t*)(Ch + o0) = h0; *(uint32_t*)(Cl + o0) = l0;
                *(uint32_t*)(Ch + o1) = h1; *(uint32_t*)(Cl + o1) = l1;
            } else {
                float* cp0 = C + (size_t)row * N + col;
                float* cp1 = C + (size_t)(row + 8) * N + col;
                *(float2*)cp0 = make_float2(acc[mi][ni][0], acc[mi][ni][1]);
                *(float2*)cp1 = make_float2(acc[mi][ni][2], acc[mi][ni][3]);
            }
        }
    }
}

// ---------------------------------------------------------------------------
// HMMA fp16 flash attention (causal; reference window term is dead code).
// S = (Qh+Ql) Kh^T, O = (Ph+Pl) Vh. K/V single fp16 tiles (half the stage).
// ---------------------------------------------------------------------------
#define AROW 144
#define A_OQH 0
#define A_OQL (128 * AROW)
#define A_STG (2 * 128 * AROW)          // 36864
#define A_TILE (64 * AROW)              // 9216
#define A_STAGE_BYTES (2 * A_TILE)      // 18432 (K, V)
#define ATT_SMEM (A_STG + 2 * A_STAGE_BYTES)   // 73728

__global__ __launch_bounds__(256) void attn_hmma(
    const __half* __restrict__ qh, const __half* __restrict__ ql,
    __half* __restrict__ yh, __half* __restrict__ yl)
{
    extern __shared__ __align__(128) char smem[];
    const uint32_t sb = smem_u32(smem);
    const int tid = threadIdx.x, lane = tid & 31, w = tid >> 5;
    const int bh = blockIdx.x, b = bh >> 4, h = bh & 15;
    const int rt = gridDim.y - 1 - blockIdx.y;
    const int r0 = rt * 128;
    const int wq0 = r0 + w * 16;

    // Q tile: hi + lo (2 x 128 rows x 128B)
    {
        const int qt = tid >> 7;
        const __half* src = qt ? ql : qh;
        const uint32_t dst = sb + (qt ? A_OQL : A_OQH);
#pragma unroll
        for (int j = 0; j < 8; j++) {
            int idx = (tid & 127) + j * 128;
            int row = idx >> 3, col = idx & 7;
            cp16(dst + row * AROW + col * 16,
                 src + ((size_t)(b * TT + r0 + row)) * C3 + h * DD + col * 8);
        }
    }
    cp_commit();

    // K/V stage: 2 single-precision tiles
    auto load_stage = [&](int buf, int k0) {
        const int t2 = tid >> 7;                  // 0: K, 1: V
        const int voff = t2 ? 2 * CC : CC;
        const uint32_t dst = sb + A_STG + buf * A_STAGE_BYTES + t2 * A_TILE;
#pragma unroll
        for (int j = 0; j < 4; j++) {
            int idx = (tid & 127) + j * 128;
            int row = idx >> 3, col = idx & 7;
            cp16(dst + row * AROW + col * 16,
                 qh + ((size_t)(b * TT + k0 + row)) * C3 + voff + h * DD + col * 8);
        }
    };

    load_stage(0, 0);
    cp_commit();
    cp_wait<1>();
    __syncthreads();

    uint32_t qfh[4][4], qfl[4][4];
    {
        const uint32_t q_row = w * 16 + (lane & 7) + ((lane >> 3) & 1) * 8;
#pragma unroll
        for (int ks = 0; ks < 4; ks++) {
            uint32_t qa = sb + A_OQH + q_row * AROW + (ks * 2 + (lane >> 4)) * 16;
            ldm_x4(qfh[ks], qa);
            ldm_x4(qfl[ks], qa + A_OQL);
        }
    }

    float o[8][4];
#pragma unroll
    for (int i = 0; i < 8; i++)
#pragma unroll
        for (int j = 0; j < 4; j++) o[i][j] = 0.f;
    float m0 = -1e30f, m1 = -1e30f, l0 = 0.f, l1 = 0.f;

    const uint32_t k_row  = (lane & 7) + (lane >> 4) * 8;
    const uint32_t k_half = (lane >> 3) & 1;
    const uint32_t v_key  = lane & 15;
    const int rg0 = wq0 + (lane >> 2), rg1 = rg0 + 8;
    const int qq2 = (lane & 3) * 2;

    const int NT = 2 * rt + 2;
    for (int ch = 0; ch < NT; ch++) {
        const int buf = ch & 1;
        if (ch + 1 < NT) {
            load_stage(buf ^ 1, (ch + 1) * 64);
            cp_commit();
            cp_wait<1>();
        } else {
            cp_wait<0>();
        }
        __syncthreads();

        const int k0 = ch * 64;
        if (k0 <= wq0) {
            const uint32_t stg = sb + A_STG + buf * A_STAGE_BYTES;

            float s[8][4];
#pragma unroll
            for (int i = 0; i < 8; i++)
#pragma unroll
                for (int j = 0; j < 4; j++) s[i][j] = 0.f;

            // S = Q Kh^T (2 products: Qh, Ql)
#pragma unroll
            for (int ks = 0; ks < 4; ks++) {
#pragma unroll
                for (int np = 0; np < 4; np++) {
                    uint32_t ka = stg + (np * 16 + k_row) * AROW
                                + (ks * 2 + k_half) * 16;
                    uint32_t kh4[4];
                    ldm_x4(kh4, ka);
                    mma16816(s[2*np],   qfh[ks], kh4);
                    mma16816(s[2*np+1], qfh[ks], kh4 + 2);
                    mma16816(s[2*np],   qfl[ks], kh4);
                    mma16816(s[2*np+1], qfl[ks], kh4 + 2);
                }
            }

            const bool need_mask = (wq0 - k0) < 64;
#pragma unroll
            for (int ni = 0; ni < 8; ni++) {
                int col = k0 + ni * 8 + qq2;
                float v0 = s[ni][0] * 0.125f, v1 = s[ni][1] * 0.125f;
                float v2 = s[ni][2] * 0.125f, v3 = s[ni][3] * 0.125f;
                if (need_mask) {
                    if (col     > rg0) v0 = -1e30f;
                    if (col + 1 > rg0) v1 = -1e30f;
                    if (col     > rg1) v2 = -1e30f;
                    if (col + 1 > rg1) v3 = -1e30f;
                }
                s[ni][0] = v0; s[ni][1] = v1; s[ni][2] = v2; s[ni][3] = v3;
            }

            float mx0 = -1e30f, mx1 = -1e30f;
#pragma unroll
            for (int ni = 0; ni < 8; ni++) {
                mx0 = fmaxf(mx0, fmaxf(s[ni][0], s[ni][1]));
                mx1 = fmaxf(mx1, fmaxf(s[ni][2], s[ni][3]));
            }
            mx0 = fmaxf(mx0, __shfl_xor_sync(0xffffffffu, mx0, 1));
            mx0 = fmaxf(mx0, __shfl_xor_sync(0xffffffffu, mx0, 2));
            mx1 = fmaxf(mx1, __shfl_xor_sync(0xffffffffu, mx1, 1));
            mx1 = fmaxf(mx1, __shfl_xor_sync(0xffffffffu, mx1, 2));

            float nm0 = fmaxf(m0, mx0), nm1 = fmaxf(m1, mx1);
            float cr0 = __expf(m0 - nm0), cr1 = __expf(m1 - nm1);
            float ps0 = 0.f, ps1 = 0.f;
#pragma unroll
            for (int ni = 0; ni < 8; ni++) {
                s[ni][0] = __expf(s[ni][0] - nm0);
                s[ni][1] = __expf(s[ni][1] - nm0);
                s[ni][2] = __expf(s[ni][2] - nm1);
                s[ni][3] = __expf(s[ni][3] - nm1);
                ps0 += s[ni][0] + s[ni][1];
                ps1 += s[ni][2] + s[ni][3];
            }
            ps0 += __shfl_xor_sync(0xffffffffu, ps0, 1);
            ps0 += __shfl_xor_sync(0xffffffffu, ps0, 2);
            ps1 += __shfl_xor_sync(0xffffffffu, ps1, 1);
            ps1 += __shfl_xor_sync(0xffffffffu, ps1, 2);
            l0 = l0 * cr0 + ps0;  l1 = l1 * cr1 + ps1;
            m0 = nm0;  m1 = nm1;
#pragma unroll
            for (int nd = 0; nd < 8; nd++) {
                o[nd][0] *= cr0; o[nd][1] *= cr0;
                o[nd][2] *= cr1; o[nd][3] *= cr1;
            }

            // O += P Vh (2 products: Ph, Pl); P frags from S registers
#pragma unroll
            for (int ks = 0; ks < 4; ks++) {
                uint32_t ph[4], pl[4];
                split_pack2(s[2*ks][0],   s[2*ks][1],   ph[0], pl[0]);
                split_pack2(s[2*ks][2],   s[2*ks][3],   ph[1], pl[1]);
                split_pack2(s[2*ks+1][0], s[2*ks+1][1], ph[2], pl[2]);
                split_pack2(s[2*ks+1][2], s[2*ks+1][3], ph[3], pl[3]);
#pragma unroll
                for (int np = 0; np < 4; np++) {
                    uint32_t va = stg + A_TILE + (ks * 16 + v_key) * AROW
                                + (np * 2 + (lane >> 4)) * 16;
                    uint32_t vh4[4];
                    ldm_x4_t(vh4, va);
                    mma16816(o[2*np],   ph, vh4);
                    mma16816(o[2*np+1], ph, vh4 + 2);
                    mma16816(o[2*np],   pl, vh4);
                    mma16816(o[2*np+1], pl, vh4 + 2);
                }
            }
        }
        __syncthreads();
    }

    const float i0 = 1.f / l0, i1 = 1.f / l1;
    const size_t ob = ((size_t)(b * TT + rg0)) * CC + h * DD + qq2;
#pragma unroll
    for (int nd = 0; nd < 8; nd++) {
        uint32_t h0, lo0, h1, lo1;
        split_pack2(o[nd][0] * i0, o[nd][1] * i0, h0, lo0);
        split_pack2(o[nd][2] * i1, o[nd][3] * i1, h1, lo1);
        *(uint32_t*)(yh + ob + nd * 8) = h0;
        *(uint32_t*)(yl + ob + nd * 8) = lo0;
        *(uint32_t*)(yh + ob + 8 * CC + nd * 8) = h1;
        *(uint32_t*)(yl + ob + 8 * CC + nd * 8) = lo1;
    }
}

// ---------------------------------------------------------------------------
extern "C" void kernel_launch(void* const* d_in, const int* in_sizes, int n_in,
                              void* d_out, int out_size)
{
    const float* x      = (const float*)d_in[0];
    const float* w_qkv  = (const float*)d_in[1];
    const float* w_proj = (const float*)d_in[2];
    float* out = (float*)d_out;

    void *pqh, *pql, *pxh, *pxl, *pwq, *pwp, *pyh, *pyl;
    cudaGetSymbolAddress(&pqh, g_qkvh); cudaGetSymbolAddress(&pql, g_qkvl);
    cudaGetSymbolAddress(&pxh, g_xh);   cudaGetSymbolAddress(&pxl, g_xl);
    cudaGetSymbolAddress(&pwq, g_wqkvT);
    cudaGetSymbolAddress(&pwp, g_wprojT);
    cudaGetSymbolAddress(&pyh, g_yh);   cudaGetSymbolAddress(&pyl, g_yl);

    cudaFuncSetAttribute(gemm_hmma<true>,
                         cudaFuncAttributeMaxDynamicSharedMemorySize, GEMM_SMEM);
    cudaFuncSetAttribute(gemm_hmma<false>,
                         cudaFuncAttributeMaxDynamicSharedMemorySize, GEMM_SMEM);
    cudaFuncSetAttribute(attn_hmma,
                         cudaFuncAttributeMaxDynamicSharedMemorySize, ATT_SMEM);

    convert_hl<<<(MM * CC) / (256 * 4), 256>>>(x, (__half*)pxh, (__half*)pxl);
    dim3 tcb(32, 8);
    transpose_convert<<<dim3(C3 / 32, CC / 32), tcb>>>(w_qkv, (__half*)pwq, CC, C3);
    transpose_convert<<<dim3(CC / 32, CC / 32), tcb>>>(w_proj, (__half*)pwp, CC, CC);

    gemm_hmma<true><<<dim3(C3 / 128, MM / 128), 128, GEMM_SMEM>>>(
        (const __half*)pxh, (const __half*)pxl, (const __half*)pwq,
        nullptr, (__half*)pqh, (__half*)pql, MM, C3, CC);

    attn_hmma<<<dim3(BB * HH, TT / 128), 256, ATT_SMEM>>>(
        (const __half*)pqh, (const __half*)pql,
        (__half*)pyh, (__half*)pyl);

    gemm_hmma<false><<<dim3(CC / 128, MM / 128), 128, GEMM_SMEM>>>(
        (const __half*)pyh, (const __half*)pyl, (const __half*)pwp,
        out, nullptr, nullptr, MM, CC, CC);
}